// round 1
// baseline (speedup 1.0000x reference)
#include <cuda_runtime.h>
#include <cuda_bf16.h>
#include <math_constants.h>

// Problem constants (fixed by dataset)
constexpr int Bq = 2, S = 2048, E = 1024, C = 16, NH = 16;
constexpr long SE = (long)S * E;          // 2,097,152
constexpr long SS = (long)S * S;          // 4,194,304
constexpr int BS = Bq * S;                // 4096
constexpr int E3 = 3 * E;                 // 3072

// ------------------------- scratch (device globals) -------------------------
__device__ float g_xd  [Bq * SE];
__device__ float g_t1  [Bq * SE];
__device__ float g_t2  [Bq * SE];
__device__ float g_sre [Bq * SE];
__device__ float g_sim [Bq * SE];
__device__ float g_chre[BS * C];
__device__ float g_chim[BS * C];
__device__ float g_mre [Bq * SE];
__device__ float g_mim [Bq * SE];
__device__ float g_scre[Bq * SS];
__device__ float g_scim[Bq * SS];
__device__ float g_ore [Bq * SE];
__device__ float g_oim [Bq * SE];
__device__ float g_stack[(long)BS * E3];
__device__ float g_qkv [(long)BS * 3 * E3];
__device__ float g_attn[(long)BS * 3 * E];
__device__ float g_corr[(long)BS * 3 * E];
__device__ float g_fw  [3 * C * E];
__device__ float g_Dm  [SS];
__device__ float g_Im  [SS];

// ------------------------------- GEMM --------------------------------------
// C[m,n] = alpha * sum_k A[m,k] * (TB ? B[n,k] : B[k,n]) + beta*C + bias[n]
template <bool TB>
__global__ __launch_bounds__(256)
void gemm_k(const float* __restrict__ A, const float* __restrict__ B,
            float* __restrict__ Cc, const float* __restrict__ bias,
            int M, int N, int K, int lda, int ldb, int ldc,
            long sA, long sB, long sC, float alpha, float beta)
{
    __shared__ float As[16][132];
    __shared__ float Bs[16][132];
    const int bm = blockIdx.y * 128, bn = blockIdx.x * 128;
    const int z = blockIdx.z;
    A += (long)z * sA; B += (long)z * sB; Cc += (long)z * sC;
    const int tid = threadIdx.x;
    const int tm = (tid >> 4) * 8, tn = (tid & 15) * 8;

    float acc[8][8];
#pragma unroll
    for (int i = 0; i < 8; i++)
#pragma unroll
        for (int j = 0; j < 8; j++) acc[i][j] = 0.f;

    const int a_m = tid >> 1, a_k = (tid & 1) * 8;

    for (int k0 = 0; k0 < K; k0 += 16) {
        // load A tile (transposed into shared)
        {
            const int m = bm + a_m;
            if (m < M) {
                const float* p = A + (long)m * lda + k0 + a_k;
#pragma unroll
                for (int j = 0; j < 8; j++) As[a_k + j][a_m] = p[j];
            } else {
#pragma unroll
                for (int j = 0; j < 8; j++) As[a_k + j][a_m] = 0.f;
            }
        }
        // load B tile
        if (!TB) {
            const int kk = tid >> 4, nn = (tid & 15) * 8;
            const int n = bn + nn;
            const float* p = B + (long)(k0 + kk) * ldb + n;
#pragma unroll
            for (int j = 0; j < 8; j++) Bs[kk][nn + j] = (n + j < N) ? p[j] : 0.f;
        } else {
            const int nn = tid >> 1, kk = (tid & 1) * 8;
            const int n = bn + nn;
            if (n < N) {
                const float* p = B + (long)n * ldb + k0 + kk;
#pragma unroll
                for (int j = 0; j < 8; j++) Bs[kk + j][nn] = p[j];
            } else {
#pragma unroll
                for (int j = 0; j < 8; j++) Bs[kk + j][nn] = 0.f;
            }
        }
        __syncthreads();
#pragma unroll
        for (int k = 0; k < 16; k++) {
            float4 a0 = *(const float4*)&As[k][tm];
            float4 a1 = *(const float4*)&As[k][tm + 4];
            float4 b0 = *(const float4*)&Bs[k][tn];
            float4 b1 = *(const float4*)&Bs[k][tn + 4];
            float av[8] = {a0.x, a0.y, a0.z, a0.w, a1.x, a1.y, a1.z, a1.w};
            float bv[8] = {b0.x, b0.y, b0.z, b0.w, b1.x, b1.y, b1.z, b1.w};
#pragma unroll
            for (int i = 0; i < 8; i++)
#pragma unroll
                for (int j = 0; j < 8; j++) acc[i][j] += av[i] * bv[j];
        }
        __syncthreads();
    }
    // epilogue
#pragma unroll
    for (int i = 0; i < 8; i++) {
        const int m = bm + tm + i;
        if (m >= M) continue;
        float* cp = Cc + (long)m * ldc;
#pragma unroll
        for (int j = 0; j < 8; j++) {
            const int n = bn + tn + j;
            if (n >= N) continue;
            float v = alpha * acc[i][j];
            if (beta != 0.f) v += beta * cp[n];
            if (bias) v += bias[n];
            cp[n] = v;
        }
    }
}

// ------------------------------ transposes ---------------------------------
// in: [Z, R, Cc] contiguous.  out[z*sO + c*ldo + off + r]
__global__ void transpose_k(const float* __restrict__ in, float* __restrict__ out,
                            int R, int Cc, long sO, int ldo, int off)
{
    __shared__ float tile[32][33];
    const int r0 = blockIdx.y * 32, c0 = blockIdx.x * 32, z = blockIdx.z;
    const float* ip = in + (long)z * R * Cc;
#pragma unroll
    for (int i = threadIdx.y; i < 32; i += 8) {
        const int r = r0 + i, c = c0 + threadIdx.x;
        tile[i][threadIdx.x] = (r < R && c < Cc) ? ip[(long)r * Cc + c] : 0.f;
    }
    __syncthreads();
#pragma unroll
    for (int i = threadIdx.y; i < 32; i += 8) {
        const int c = c0 + i, r = r0 + threadIdx.x;
        if (c < Cc && r < R)
            out[(long)z * sO + (long)c * ldo + off + r] = tile[threadIdx.x][i];
    }
}

// ------------------------------- FFT ---------------------------------------
// 2048-pt radix-2 FFT per row (rows contiguous).  in_im may be null.
__global__ __launch_bounds__(512)
void fft_k(const float* __restrict__ ir, const float* __restrict__ ii,
           float* __restrict__ outr, float* __restrict__ outi, int inverse)
{
    __shared__ float sr[2048], si[2048];
    const long base = (long)blockIdx.x * 2048;
    const int tid = threadIdx.x;
    for (int i = tid; i < 2048; i += 512) {
        const int j = __brev((unsigned)i) >> 21;
        sr[j] = ir[base + i];
        si[j] = ii ? ii[base + i] : 0.f;
    }
    const float sgn = inverse ? 1.f : -1.f;
    for (int st = 1; st <= 11; st++) {
        __syncthreads();
        const int half = 1 << (st - 1);
#pragma unroll 1
        for (int t = tid; t < 1024; t += 512) {
            const int j = t & (half - 1);
            const int i0 = ((t >> (st - 1)) << st) + j;
            const int i1 = i0 + half;
            const float x = (float)j / (float)half;   // exact dyadic
            float wi, wr;
            sincospif(x, &wi, &wr);
            wi *= sgn;
            const float vr = sr[i1], vi = si[i1];
            const float tr = vr * wr - vi * wi;
            const float ti = vr * wi + vi * wr;
            const float ur = sr[i0], ui = si[i0];
            sr[i0] = ur + tr; si[i0] = ui + ti;
            sr[i1] = ur - tr; si[i1] = ui - ti;
        }
    }
    __syncthreads();
    const float sc = inverse ? (1.f / 2048.f) : 1.f;
    for (int i = tid; i < 2048; i += 512) {
        outr[base + i] = sr[i] * sc;
        outi[base + i] = si[i] * sc;
    }
}

// ------------------------------- Haar --------------------------------------
__global__ __launch_bounds__(512)
void haar_k(const float* __restrict__ in, float* __restrict__ out)
{
    __shared__ float bufA[2048], bufB[2048];
    const long base = (long)blockIdx.x * 2048;
    const int tid = threadIdx.x;
    for (int i = tid; i < 2048; i += 512) bufA[i] = in[base + i];
    float* cur = bufA; float* nxt = bufB;
    const float R2 = 0.70710678118654752f;
    for (int L = 2048; L > 1; L >>= 1) {
        const int half = L >> 1;
        __syncthreads();
        for (int t = tid; t < half; t += 512) {
            const float e = cur[2 * t], o = cur[2 * t + 1];
            out[base + half + t] = (e - o) * R2;
            nxt[t] = (e + o) * R2;
        }
        float* tmp = cur; cur = nxt; nxt = tmp;
    }
    __syncthreads();
    if (tid == 0) out[base] = cur[0];
}

// --------------------------- conv1d (E -> C, k=3) ---------------------------
// x: [Bq,S,E]; Wc: [C,E,3]; ch: [Bq*S, C]
__global__ __launch_bounds__(128)
void conv_k(const float* __restrict__ x, const float* __restrict__ Wc,
            const float* __restrict__ bc, float* __restrict__ ch)
{
    __shared__ float sh[10][1024];
    const int blk = blockIdx.x;                  // 512 blocks of 8 s each
    const int b = (blk * 8) / S;
    const int s0 = (blk * 8) % S;
    const float* xb = x + (long)b * S * E;
    const int tid = threadIdx.x;
    for (int i = tid; i < 10 * 1024; i += 128) {
        const int row = i >> 10, col = i & 1023;
        const int s = s0 - 1 + row;
        sh[row][col] = (s >= 0 && s < S) ? xb[(long)s * E + col] : 0.f;
    }
    __syncthreads();
    const int sl = tid >> 4, c = tid & 15;
    const float* w = Wc + c * (E * 3);
    float acc = bc[c];
#pragma unroll 1
    for (int e = 0; e < E; e++) {
        const float w0 = w[e * 3], w1 = w[e * 3 + 1], w2 = w[e * 3 + 2];
        acc += sh[sl][e] * w0 + sh[sl + 1][e] * w1 + sh[sl + 2][e] * w2;
    }
    ch[(long)(b * S + s0 + sl) * C + c] = acc;
}

// ------------------------------ softmax ------------------------------------
__global__ __launch_bounds__(256)
void softmax_real_k(float* __restrict__ sc)
{
    __shared__ float row[2048];
    __shared__ float red[256];
    const long base = (long)blockIdx.x * 2048;
    const int tid = threadIdx.x;
    float m = -CUDART_INF_F;
    for (int i = tid; i < 2048; i += 256) { const float v = sc[base + i]; row[i] = v; m = fmaxf(m, v); }
    red[tid] = m; __syncthreads();
    for (int s = 128; s > 0; s >>= 1) { if (tid < s) red[tid] = fmaxf(red[tid], red[tid + s]); __syncthreads(); }
    m = red[0]; __syncthreads();
    float sum = 0.f;
    for (int i = tid; i < 2048; i += 256) { const float e = expf(row[i] - m); row[i] = e; sum += e; }
    red[tid] = sum; __syncthreads();
    for (int s = 128; s > 0; s >>= 1) { if (tid < s) red[tid] += red[tid + s]; __syncthreads(); }
    const float inv = 1.f / red[0];
    for (int i = tid; i < 2048; i += 256) sc[base + i] = row[i] * inv;
}

__global__ __launch_bounds__(256)
void softmax_cplx_k(float* __restrict__ re, float* __restrict__ im)
{
    __shared__ float rr[2048], ri[2048];
    __shared__ float red[256];
    const long base = (long)blockIdx.x * 2048;
    const int tid = threadIdx.x;
    float m = -CUDART_INF_F;
    for (int i = tid; i < 2048; i += 256) {
        const float v = re[base + i]; rr[i] = v; ri[i] = im[base + i]; m = fmaxf(m, v);
    }
    red[tid] = m; __syncthreads();
    for (int s = 128; s > 0; s >>= 1) { if (tid < s) red[tid] = fmaxf(red[tid], red[tid + s]); __syncthreads(); }
    m = red[0]; __syncthreads();
    float sum = 0.f;
    for (int i = tid; i < 2048; i += 256) sum += expf(rr[i] - m);
    red[tid] = sum; __syncthreads();
    for (int s = 128; s > 0; s >>= 1) { if (tid < s) red[tid] += red[tid + s]; __syncthreads(); }
    const float inv = 1.f / red[0];
    for (int i = tid; i < 2048; i += 256) {
        const float r = rr[i], q = ri[i];
        const float w = expf(r - m) * inv;
        const float mag = sqrtf(r * r + q * q);
        if (mag > 0.f) {
            const float invm = w / mag;
            re[base + i] = r * invm;
            im[base + i] = q * invm;
        } else {
            re[base + i] = w;
            im[base + i] = 0.f;
        }
    }
}

// --------------------------- small weight prep ------------------------------
__global__ void fwsoft_k(const float* __restrict__ F, float* __restrict__ fw)
{
    const int e = blockIdx.x * 256 + threadIdx.x;
    if (e >= E) return;
    float m = -CUDART_INF_F;
#pragma unroll
    for (int c = 0; c < C; c++) m = fmaxf(m, F[c * E + e]);
    float v[C]; float s = 0.f;
#pragma unroll
    for (int c = 0; c < C; c++) { v[c] = expf(F[c * E + e] - m); s += v[c]; }
    const float inv = 1.f / s;
#pragma unroll
    for (int c = 0; c < C; c++) fw[c * E + e] = v[c] * inv;
}

__global__ void dctinit_k(float* __restrict__ D, float* __restrict__ I)
{
    const long idx = (long)blockIdx.x * 256 + threadIdx.x;
    if (idx >= SS) return;
    const int a = (int)(idx >> 11), b = (int)(idx & 2047);
    const float s1 = 0.022097086912079610f;   // sqrt(1/2048)
    const float s2 = 0.03125f;                // sqrt(2/2048)
    const int m1 = (a * (2 * b + 1)) & 8191;  // exact: arg < 2^24
    D[idx] = cospif((float)m1 * (1.f / 4096.f)) * (a == 0 ? s1 : s2);
    const int m2 = (b * (2 * a + 1)) & 8191;
    I[idx] = cospif((float)m2 * (1.f / 4096.f)) * (b == 0 ? s1 : s2);
}

// ------------------------------ tiny MHA (L=3) ------------------------------
__global__ __launch_bounds__(256)
void mha_k(const float* __restrict__ qkv, float* __restrict__ attn)
{
    const int warp = (blockIdx.x * blockDim.x + threadIdx.x) >> 5;
    const int lane = threadIdx.x & 31;
    const int bx = warp >> 4, h = warp & 15;
    if (bx >= BS) return;
    const float* base = qkv + (long)bx * 3 * E3 + h * 64;
    float q[3][2], k[3][2], v[3][2];
#pragma unroll
    for (int l = 0; l < 3; l++) {
        const float* p = base + (long)l * E3;
        q[l][0] = p[lane];        q[l][1] = p[lane + 32];
        k[l][0] = p[E + lane];    k[l][1] = p[E + lane + 32];
        v[l][0] = p[2 * E + lane]; v[l][1] = p[2 * E + lane + 32];
    }
    float s[3][3];
#pragma unroll
    for (int l = 0; l < 3; l++)
#pragma unroll
        for (int mI = 0; mI < 3; mI++) {
            float p = q[l][0] * k[mI][0] + q[l][1] * k[mI][1];
#pragma unroll
            for (int o = 16; o; o >>= 1) p += __shfl_xor_sync(0xFFFFFFFF, p, o);
            s[l][mI] = p * 0.125f;
        }
#pragma unroll
    for (int l = 0; l < 3; l++) {
        const float mx = fmaxf(s[l][0], fmaxf(s[l][1], s[l][2]));
        const float e0 = expf(s[l][0] - mx), e1 = expf(s[l][1] - mx), e2 = expf(s[l][2] - mx);
        const float inv = 1.f / (e0 + e1 + e2);
        const float a0 = e0 * inv, a1 = e1 * inv, a2 = e2 * inv;
        const float o0 = a0 * v[0][0] + a1 * v[1][0] + a2 * v[2][0];
        const float o1 = a0 * v[0][1] + a1 * v[1][1] + a2 * v[2][1];
        float* op = attn + (long)(bx * 3 + l) * E + h * 64;
        op[lane] = o0;
        op[lane + 32] = o1;
    }
}

// ------------------------------- host --------------------------------------
static inline dim3 ggrid(int M, int N, int batch)
{
    return dim3((N + 127) / 128, (M + 127) / 128, batch);
}

extern "C" void kernel_launch(void* const* d_in, const int* in_sizes, int n_in,
                              void* d_out, int out_size)
{
    const float* query  = (const float*)d_in[0];
    const float* Wp[3]  = {(const float*)d_in[1], (const float*)d_in[6],  (const float*)d_in[11]};
    const float* bp[3]  = {(const float*)d_in[2], (const float*)d_in[7],  (const float*)d_in[12]};
    const float* Wc[3]  = {(const float*)d_in[3], (const float*)d_in[8],  (const float*)d_in[13]};
    const float* bc[3]  = {(const float*)d_in[4], (const float*)d_in[9],  (const float*)d_in[14]};
    const float* Fp[3]  = {(const float*)d_in[5], (const float*)d_in[10], (const float*)d_in[15]};
    const float* mha_iw = (const float*)d_in[16];
    const float* mha_ib = (const float*)d_in[17];
    const float* mha_ow = (const float*)d_in[18];
    const float* mha_ob = (const float*)d_in[19];
    const float* fus_W  = (const float*)d_in[20];
    const float* fus_b  = (const float*)d_in[21];
    float* outp = (float*)d_out;

    float *xd, *t1, *t2, *sre, *sim, *chre, *chim, *mre, *mim;
    float *scre, *scim, *ore, *oim, *stack, *qkvb, *attnb, *corr, *fw, *Dm, *Im;
    cudaGetSymbolAddress((void**)&xd, g_xd);
    cudaGetSymbolAddress((void**)&t1, g_t1);
    cudaGetSymbolAddress((void**)&t2, g_t2);
    cudaGetSymbolAddress((void**)&sre, g_sre);
    cudaGetSymbolAddress((void**)&sim, g_sim);
    cudaGetSymbolAddress((void**)&chre, g_chre);
    cudaGetSymbolAddress((void**)&chim, g_chim);
    cudaGetSymbolAddress((void**)&mre, g_mre);
    cudaGetSymbolAddress((void**)&mim, g_mim);
    cudaGetSymbolAddress((void**)&scre, g_scre);
    cudaGetSymbolAddress((void**)&scim, g_scim);
    cudaGetSymbolAddress((void**)&ore, g_ore);
    cudaGetSymbolAddress((void**)&oim, g_oim);
    cudaGetSymbolAddress((void**)&stack, g_stack);
    cudaGetSymbolAddress((void**)&qkvb, g_qkv);
    cudaGetSymbolAddress((void**)&attnb, g_attn);
    cudaGetSymbolAddress((void**)&corr, g_corr);
    cudaGetSymbolAddress((void**)&fw, g_fw);
    cudaGetSymbolAddress((void**)&Dm, g_Dm);
    cudaGetSymbolAddress((void**)&Im, g_Im);

    const float scale = 0.03125f;  // 1/sqrt(1024)

    // setup
    dctinit_k<<<(int)((SS + 255) / 256), 256>>>(Dm, Im);
    for (int d = 0; d < 3; d++)
        fwsoft_k<<<(E + 255) / 256, 256>>>(Fp[d], fw + (long)d * C * E);

    const dim3 tpb_t(32, 8);

    for (int d = 0; d < 3; d++) {
        const float* fwd = fw + (long)d * C * E;
        // projection: xd = query @ Wp^T + bp   [4096,1024]
        gemm_k<true><<<ggrid(BS, E, 1), 256>>>(query, Wp[d], xd, bp[d],
            BS, E, E, E, E, E, 0, 0, 0, 1.f, 0.f);

        if (d == 0) {
            // ---- Fourier ----
            transpose_k<<<dim3(E / 32, S / 32, Bq), tpb_t>>>(xd, t1, S, E, SE, S, 0);
            fft_k<<<Bq * E, 512>>>(t1, nullptr, t1, t2, 0);
            transpose_k<<<dim3(S / 32, E / 32, Bq), tpb_t>>>(t1, sre, E, S, SE, E, 0);
            transpose_k<<<dim3(S / 32, E / 32, Bq), tpb_t>>>(t2, sim, E, S, SE, E, 0);
            conv_k<<<BS / 8, 128>>>(sre, Wc[d], bc[d], chre);
            conv_k<<<BS / 8, 128>>>(sim, Wc[d], bc[d], chim);
            gemm_k<false><<<ggrid(BS, E, 1), 256>>>(chre, fwd, mre, nullptr,
                BS, E, C, C, E, E, 0, 0, 0, 1.f, 0.f);
            gemm_k<false><<<ggrid(BS, E, 1), 256>>>(chim, fwd, mim, nullptr,
                BS, E, C, C, E, E, 0, 0, 0, 1.f, 0.f);
            // complex scores
            gemm_k<true><<<ggrid(S, S, Bq), 256>>>(mre, mre, scre, nullptr,
                S, S, E, E, E, S, SE, SE, SS, scale, 0.f);
            gemm_k<true><<<ggrid(S, S, Bq), 256>>>(mim, mim, scre, nullptr,
                S, S, E, E, E, S, SE, SE, SS, -scale, 1.f);
            gemm_k<true><<<ggrid(S, S, Bq), 256>>>(mre, mim, scim, nullptr,
                S, S, E, E, E, S, SE, SE, SS, scale, 0.f);
            gemm_k<true><<<ggrid(S, S, Bq), 256>>>(mim, mre, scim, nullptr,
                S, S, E, E, E, S, SE, SE, SS, scale, 1.f);
            softmax_cplx_k<<<BS, 256>>>(scre, scim);
            // complex out = cw @ v
            gemm_k<false><<<ggrid(S, E, Bq), 256>>>(scre, mre, ore, nullptr,
                S, E, S, S, E, E, SS, SE, SE, 1.f, 0.f);
            gemm_k<false><<<ggrid(S, E, Bq), 256>>>(scim, mim, ore, nullptr,
                S, E, S, S, E, E, SS, SE, SE, -1.f, 1.f);
            gemm_k<false><<<ggrid(S, E, Bq), 256>>>(scre, mim, oim, nullptr,
                S, E, S, S, E, E, SS, SE, SE, 1.f, 0.f);
            gemm_k<false><<<ggrid(S, E, Bq), 256>>>(scim, mre, oim, nullptr,
                S, E, S, S, E, E, SS, SE, SE, 1.f, 1.f);
            // ifft, take real, write into stack slot 0
            transpose_k<<<dim3(E / 32, S / 32, Bq), tpb_t>>>(ore, t1, S, E, SE, S, 0);
            transpose_k<<<dim3(E / 32, S / 32, Bq), tpb_t>>>(oim, t2, S, E, SE, S, 0);
            fft_k<<<Bq * E, 512>>>(t1, t2, t1, t2, 1);
            transpose_k<<<dim3(S / 32, E / 32, Bq), tpb_t>>>(t1, stack, E, S, (long)S * E3, E3, 0);
        } else if (d == 1) {
            // ---- Wavelet ----
            transpose_k<<<dim3(E / 32, S / 32, Bq), tpb_t>>>(xd, t1, S, E, SE, S, 0);
            haar_k<<<Bq * E, 512>>>(t1, t2);
            transpose_k<<<dim3(S / 32, E / 32, Bq), tpb_t>>>(t2, sre, E, S, SE, E, 0);
            conv_k<<<BS / 8, 128>>>(sre, Wc[d], bc[d], chre);
            gemm_k<false><<<ggrid(BS, E, 1), 256>>>(chre, fwd, mre, nullptr,
                BS, E, C, C, E, E, 0, 0, 0, 1.f, 0.f);
            gemm_k<true><<<ggrid(S, S, Bq), 256>>>(mre, mre, scre, nullptr,
                S, S, E, E, E, S, SE, SE, SS, scale, 0.f);
            softmax_real_k<<<BS, 256>>>(scre);
            gemm_k<false><<<ggrid(S, E, Bq), 256>>>(scre, mre, stack + E, nullptr,
                S, E, S, S, E, E3, SS, SE, (long)S * E3, 1.f, 0.f);
        } else {
            // ---- Cosine ----
            gemm_k<false><<<ggrid(S, E, Bq), 256>>>(Dm, xd, sre, nullptr,
                S, E, S, S, E, E, 0, SE, SE, 1.f, 0.f);
            conv_k<<<BS / 8, 128>>>(sre, Wc[d], bc[d], chre);
            gemm_k<false><<<ggrid(BS, E, 1), 256>>>(chre, fwd, mre, nullptr,
                BS, E, C, C, E, E, 0, 0, 0, 1.f, 0.f);
            gemm_k<true><<<ggrid(S, S, Bq), 256>>>(mre, mre, scre, nullptr,
                S, S, E, E, E, S, SE, SE, SS, scale, 0.f);
            softmax_real_k<<<BS, 256>>>(scre);
            gemm_k<false><<<ggrid(S, E, Bq), 256>>>(scre, mre, ore, nullptr,
                S, E, S, S, E, E, SS, SE, SE, 1.f, 0.f);
            gemm_k<false><<<ggrid(S, E, Bq), 256>>>(Im, ore, stack + 2 * E, nullptr,
                S, E, S, S, E, E3, 0, SE, (long)S * E3, 1.f, 0.f);
        }
    }

    // ---- cross-domain MHA over L=3 ----
    gemm_k<true><<<ggrid(BS * 3, E3, 1), 256>>>(stack, mha_iw, qkvb, mha_ib,
        BS * 3, E3, E, E, E, E3, 0, 0, 0, 1.f, 0.f);
    mha_k<<<(BS * NH) / 8, 256>>>(qkvb, attnb);
    gemm_k<true><<<ggrid(BS * 3, E, 1), 256>>>(attnb, mha_ow, corr, mha_ob,
        BS * 3, E, E, E, E, E, 0, 0, 0, 1.f, 0.f);
    gemm_k<true><<<ggrid(BS, E, 1), 256>>>(corr, fus_W, outp, fus_b,
        BS, E, E3, E3, E3, E, 0, 0, 0, 1.f, 0.f);
}

// round 2
// speedup vs baseline: 1.0007x; 1.0007x over previous
#include <cuda_runtime.h>
#include <cuda_bf16.h>
#include <math_constants.h>

// Problem constants (fixed by dataset)
constexpr int Bq = 2, S = 2048, E = 1024, C = 16, NH = 16;
constexpr long SE = (long)S * E;          // 2,097,152
constexpr long SS = (long)S * S;          // 4,194,304
constexpr int BS = Bq * S;                // 4096
constexpr int E3 = 3 * E;                 // 3072

// ------------------------- scratch (device globals) -------------------------
__device__ float g_xd  [Bq * SE];
__device__ float g_t1  [Bq * SE];
__device__ float g_t2  [Bq * SE];
__device__ float g_sre [Bq * SE];
__device__ float g_sim [Bq * SE];
__device__ float g_chre[BS * C];
__device__ float g_chim[BS * C];
__device__ float g_mre [Bq * SE];
__device__ float g_mim [Bq * SE];
__device__ float g_scre[Bq * SS];
__device__ float g_scim[Bq * SS];
__device__ float g_ore [Bq * SE];
__device__ float g_oim [Bq * SE];
__device__ float g_stack[(long)BS * E3];
__device__ float g_qkv [(long)BS * 3 * E3];
__device__ float g_attn[(long)BS * 3 * E];
__device__ float g_corr[(long)BS * 3 * E];
__device__ float g_fw  [3 * C * E];
__device__ float g_Dm  [SS];
__device__ float g_Im  [SS];

// ------------------------------- GEMM --------------------------------------
// C[m,n] = alpha * sum_k A[m,k] * (TB ? B[n,k] : B[k,n]) + beta*C + bias[n]
template <bool TB>
__global__ __launch_bounds__(256)
void gemm_k(const float* __restrict__ A, const float* __restrict__ B,
            float* __restrict__ Cc, const float* __restrict__ bias,
            int M, int N, int K, int lda, int ldb, int ldc,
            long sA, long sB, long sC, float alpha, float beta)
{
    __shared__ float As[16][132];
    __shared__ float Bs[16][132];
    const int bm = blockIdx.y * 128, bn = blockIdx.x * 128;
    const int z = blockIdx.z;
    A += (long)z * sA; B += (long)z * sB; Cc += (long)z * sC;
    const int tid = threadIdx.x;
    const int tm = (tid >> 4) * 8, tn = (tid & 15) * 8;

    float acc[8][8];
#pragma unroll
    for (int i = 0; i < 8; i++)
#pragma unroll
        for (int j = 0; j < 8; j++) acc[i][j] = 0.f;

    const int a_m = tid >> 1, a_k = (tid & 1) * 8;

    for (int k0 = 0; k0 < K; k0 += 16) {
        // load A tile (transposed into shared)
        {
            const int m = bm + a_m;
            if (m < M) {
                const float* p = A + (long)m * lda + k0 + a_k;
#pragma unroll
                for (int j = 0; j < 8; j++) As[a_k + j][a_m] = p[j];
            } else {
#pragma unroll
                for (int j = 0; j < 8; j++) As[a_k + j][a_m] = 0.f;
            }
        }
        // load B tile
        if (!TB) {
            const int kk = tid >> 4, nn = (tid & 15) * 8;
            const int n = bn + nn;
            const float* p = B + (long)(k0 + kk) * ldb + n;
#pragma unroll
            for (int j = 0; j < 8; j++) Bs[kk][nn + j] = (n + j < N) ? p[j] : 0.f;
        } else {
            const int nn = tid >> 1, kk = (tid & 1) * 8;
            const int n = bn + nn;
            if (n < N) {
                const float* p = B + (long)n * ldb + k0 + kk;
#pragma unroll
                for (int j = 0; j < 8; j++) Bs[kk + j][nn] = p[j];
            } else {
#pragma unroll
                for (int j = 0; j < 8; j++) Bs[kk + j][nn] = 0.f;
            }
        }
        __syncthreads();
#pragma unroll
        for (int k = 0; k < 16; k++) {
            float4 a0 = *(const float4*)&As[k][tm];
            float4 a1 = *(const float4*)&As[k][tm + 4];
            float4 b0 = *(const float4*)&Bs[k][tn];
            float4 b1 = *(const float4*)&Bs[k][tn + 4];
            float av[8] = {a0.x, a0.y, a0.z, a0.w, a1.x, a1.y, a1.z, a1.w};
            float bv[8] = {b0.x, b0.y, b0.z, b0.w, b1.x, b1.y, b1.z, b1.w};
#pragma unroll
            for (int i = 0; i < 8; i++)
#pragma unroll
                for (int j = 0; j < 8; j++) acc[i][j] += av[i] * bv[j];
        }
        __syncthreads();
    }
    // epilogue
#pragma unroll
    for (int i = 0; i < 8; i++) {
        const int m = bm + tm + i;
        if (m >= M) continue;
        float* cp = Cc + (long)m * ldc;
#pragma unroll
        for (int j = 0; j < 8; j++) {
            const int n = bn + tn + j;
            if (n >= N) continue;
            float v = alpha * acc[i][j];
            if (beta != 0.f) v += beta * cp[n];
            if (bias) v += bias[n];
            cp[n] = v;
        }
    }
}

// ------------------------------ transposes ---------------------------------
// in: [Z, R, Cc] contiguous.  out[z*sO + c*ldo + off + r]
__global__ void transpose_k(const float* __restrict__ in, float* __restrict__ out,
                            int R, int Cc, long sO, int ldo, int off)
{
    __shared__ float tile[32][33];
    const int r0 = blockIdx.y * 32, c0 = blockIdx.x * 32, z = blockIdx.z;
    const float* ip = in + (long)z * R * Cc;
#pragma unroll
    for (int i = threadIdx.y; i < 32; i += 8) {
        const int r = r0 + i, c = c0 + threadIdx.x;
        tile[i][threadIdx.x] = (r < R && c < Cc) ? ip[(long)r * Cc + c] : 0.f;
    }
    __syncthreads();
#pragma unroll
    for (int i = threadIdx.y; i < 32; i += 8) {
        const int c = c0 + i, r = r0 + threadIdx.x;
        if (c < Cc && r < R)
            out[(long)z * sO + (long)c * ldo + off + r] = tile[threadIdx.x][i];
    }
}

// ------------------------------- FFT ---------------------------------------
// 2048-pt radix-2 FFT per row (rows contiguous).  in_im may be null.
__global__ __launch_bounds__(512)
void fft_k(const float* __restrict__ ir, const float* __restrict__ ii,
           float* __restrict__ outr, float* __restrict__ outi, int inverse)
{
    __shared__ float sr[2048], si[2048];
    const long base = (long)blockIdx.x * 2048;
    const int tid = threadIdx.x;
    for (int i = tid; i < 2048; i += 512) {
        const int j = __brev((unsigned)i) >> 21;
        sr[j] = ir[base + i];
        si[j] = ii ? ii[base + i] : 0.f;
    }
    const float sgn = inverse ? 1.f : -1.f;
    for (int st = 1; st <= 11; st++) {
        __syncthreads();
        const int half = 1 << (st - 1);
#pragma unroll 1
        for (int t = tid; t < 1024; t += 512) {
            const int j = t & (half - 1);
            const int i0 = ((t >> (st - 1)) << st) + j;
            const int i1 = i0 + half;
            const float x = (float)j / (float)half;   // exact dyadic
            float wi, wr;
            sincospif(x, &wi, &wr);
            wi *= sgn;
            const float vr = sr[i1], vi = si[i1];
            const float tr = vr * wr - vi * wi;
            const float ti = vr * wi + vi * wr;
            const float ur = sr[i0], ui = si[i0];
            sr[i0] = ur + tr; si[i0] = ui + ti;
            sr[i1] = ur - tr; si[i1] = ui - ti;
        }
    }
    __syncthreads();
    const float sc = inverse ? (1.f / 2048.f) : 1.f;
    for (int i = tid; i < 2048; i += 512) {
        outr[base + i] = sr[i] * sc;
        outi[base + i] = si[i] * sc;
    }
}

// ------------------------------- Haar --------------------------------------
__global__ __launch_bounds__(512)
void haar_k(const float* __restrict__ in, float* __restrict__ out)
{
    __shared__ float bufA[2048], bufB[2048];
    const long base = (long)blockIdx.x * 2048;
    const int tid = threadIdx.x;
    for (int i = tid; i < 2048; i += 512) bufA[i] = in[base + i];
    float* cur = bufA; float* nxt = bufB;
    const float R2 = 0.70710678118654752f;
    for (int L = 2048; L > 1; L >>= 1) {
        const int half = L >> 1;
        __syncthreads();
        for (int t = tid; t < half; t += 512) {
            const float e = cur[2 * t], o = cur[2 * t + 1];
            out[base + half + t] = (e - o) * R2;
            nxt[t] = (e + o) * R2;
        }
        float* tmp = cur; cur = nxt; nxt = tmp;
    }
    __syncthreads();
    if (tid == 0) out[base] = cur[0];
}

// --------------------------- conv1d (E -> C, k=3) ---------------------------
// x: [Bq,S,E]; Wc: [C,E,3]; ch: [Bq*S, C]
__global__ __launch_bounds__(128)
void conv_k(const float* __restrict__ x, const float* __restrict__ Wc,
            const float* __restrict__ bc, float* __restrict__ ch)
{
    __shared__ float sh[10][1024];
    const int blk = blockIdx.x;                  // 512 blocks of 8 s each
    const int b = (blk * 8) / S;
    const int s0 = (blk * 8) % S;
    const float* xb = x + (long)b * S * E;
    const int tid = threadIdx.x;
    for (int i = tid; i < 10 * 1024; i += 128) {
        const int row = i >> 10, col = i & 1023;
        const int s = s0 - 1 + row;
        sh[row][col] = (s >= 0 && s < S) ? xb[(long)s * E + col] : 0.f;
    }
    __syncthreads();
    const int sl = tid >> 4, c = tid & 15;
    const float* w = Wc + c * (E * 3);
    float acc = bc[c];
#pragma unroll 1
    for (int e = 0; e < E; e++) {
        const float w0 = w[e * 3], w1 = w[e * 3 + 1], w2 = w[e * 3 + 2];
        acc += sh[sl][e] * w0 + sh[sl + 1][e] * w1 + sh[sl + 2][e] * w2;
    }
    ch[(long)(b * S + s0 + sl) * C + c] = acc;
}

// ------------------------------ softmax ------------------------------------
__global__ __launch_bounds__(256)
void softmax_real_k(float* __restrict__ sc)
{
    __shared__ float row[2048];
    __shared__ float red[256];
    const long base = (long)blockIdx.x * 2048;
    const int tid = threadIdx.x;
    float m = -CUDART_INF_F;
    for (int i = tid; i < 2048; i += 256) { const float v = sc[base + i]; row[i] = v; m = fmaxf(m, v); }
    red[tid] = m; __syncthreads();
    for (int s = 128; s > 0; s >>= 1) { if (tid < s) red[tid] = fmaxf(red[tid], red[tid + s]); __syncthreads(); }
    m = red[0]; __syncthreads();
    float sum = 0.f;
    for (int i = tid; i < 2048; i += 256) { const float e = expf(row[i] - m); row[i] = e; sum += e; }
    red[tid] = sum; __syncthreads();
    for (int s = 128; s > 0; s >>= 1) { if (tid < s) red[tid] += red[tid + s]; __syncthreads(); }
    const float inv = 1.f / red[0];
    for (int i = tid; i < 2048; i += 256) sc[base + i] = row[i] * inv;
}

__global__ __launch_bounds__(256)
void softmax_cplx_k(float* __restrict__ re, float* __restrict__ im)
{
    __shared__ float rr[2048], ri[2048];
    __shared__ float red[256];
    const long base = (long)blockIdx.x * 2048;
    const int tid = threadIdx.x;
    float m = -CUDART_INF_F;
    for (int i = tid; i < 2048; i += 256) {
        const float v = re[base + i]; rr[i] = v; ri[i] = im[base + i]; m = fmaxf(m, v);
    }
    red[tid] = m; __syncthreads();
    for (int s = 128; s > 0; s >>= 1) { if (tid < s) red[tid] = fmaxf(red[tid], red[tid + s]); __syncthreads(); }
    m = red[0]; __syncthreads();
    float sum = 0.f;
    for (int i = tid; i < 2048; i += 256) sum += expf(rr[i] - m);
    red[tid] = sum; __syncthreads();
    for (int s = 128; s > 0; s >>= 1) { if (tid < s) red[tid] += red[tid + s]; __syncthreads(); }
    const float inv = 1.f / red[0];
    for (int i = tid; i < 2048; i += 256) {
        const float r = rr[i], q = ri[i];
        const float w = expf(r - m) * inv;
        const float mag = sqrtf(r * r + q * q);
        if (mag > 0.f) {
            const float invm = w / mag;
            re[base + i] = r * invm;
            im[base + i] = q * invm;
        } else {
            re[base + i] = w;
            im[base + i] = 0.f;
        }
    }
}

// --------------------------- small weight prep ------------------------------
__global__ void fwsoft_k(const float* __restrict__ F, float* __restrict__ fw)
{
    const int e = blockIdx.x * 256 + threadIdx.x;
    if (e >= E) return;
    float m = -CUDART_INF_F;
#pragma unroll
    for (int c = 0; c < C; c++) m = fmaxf(m, F[c * E + e]);
    float v[C]; float s = 0.f;
#pragma unroll
    for (int c = 0; c < C; c++) { v[c] = expf(F[c * E + e] - m); s += v[c]; }
    const float inv = 1.f / s;
#pragma unroll
    for (int c = 0; c < C; c++) fw[c * E + e] = v[c] * inv;
}

__global__ void dctinit_k(float* __restrict__ D, float* __restrict__ I)
{
    const long idx = (long)blockIdx.x * 256 + threadIdx.x;
    if (idx >= SS) return;
    const int a = (int)(idx >> 11), b = (int)(idx & 2047);
    const float s1 = 0.022097086912079610f;   // sqrt(1/2048)
    const float s2 = 0.03125f;                // sqrt(2/2048)
    const int m1 = (a * (2 * b + 1)) & 8191;  // exact: arg < 2^24
    D[idx] = cospif((float)m1 * (1.f / 4096.f)) * (a == 0 ? s1 : s2);
    const int m2 = (b * (2 * a + 1)) & 8191;
    I[idx] = cospif((float)m2 * (1.f / 4096.f)) * (b == 0 ? s1 : s2);
}

// ------------------------------ tiny MHA (L=3) ------------------------------
__global__ __launch_bounds__(256)
void mha_k(const float* __restrict__ qkv, float* __restrict__ attn)
{
    const int warp = (blockIdx.x * blockDim.x + threadIdx.x) >> 5;
    const int lane = threadIdx.x & 31;
    const int bx = warp >> 4, h = warp & 15;
    if (bx >= BS) return;
    const float* base = qkv + (long)bx * 3 * E3 + h * 64;
    float q[3][2], k[3][2], v[3][2];
#pragma unroll
    for (int l = 0; l < 3; l++) {
        const float* p = base + (long)l * E3;
        q[l][0] = p[lane];        q[l][1] = p[lane + 32];
        k[l][0] = p[E + lane];    k[l][1] = p[E + lane + 32];
        v[l][0] = p[2 * E + lane]; v[l][1] = p[2 * E + lane + 32];
    }
    float s[3][3];
#pragma unroll
    for (int l = 0; l < 3; l++)
#pragma unroll
        for (int mI = 0; mI < 3; mI++) {
            float p = q[l][0] * k[mI][0] + q[l][1] * k[mI][1];
#pragma unroll
            for (int o = 16; o; o >>= 1) p += __shfl_xor_sync(0xFFFFFFFF, p, o);
            s[l][mI] = p * 0.125f;
        }
#pragma unroll
    for (int l = 0; l < 3; l++) {
        const float mx = fmaxf(s[l][0], fmaxf(s[l][1], s[l][2]));
        const float e0 = expf(s[l][0] - mx), e1 = expf(s[l][1] - mx), e2 = expf(s[l][2] - mx);
        const float inv = 1.f / (e0 + e1 + e2);
        const float a0 = e0 * inv, a1 = e1 * inv, a2 = e2 * inv;
        const float o0 = a0 * v[0][0] + a1 * v[1][0] + a2 * v[2][0];
        const float o1 = a0 * v[0][1] + a1 * v[1][1] + a2 * v[2][1];
        float* op = attn + (long)(bx * 3 + l) * E + h * 64;
        op[lane] = o0;
        op[lane + 32] = o1;
    }
}

// ------------------------------- host --------------------------------------
static inline dim3 ggrid(int M, int N, int batch)
{
    return dim3((N + 127) / 128, (M + 127) / 128, batch);
}

extern "C" void kernel_launch(void* const* d_in, const int* in_sizes, int n_in,
                              void* d_out, int out_size)
{
    const float* query  = (const float*)d_in[0];
    const float* Wp[3]  = {(const float*)d_in[1], (const float*)d_in[6],  (const float*)d_in[11]};
    const float* bp[3]  = {(const float*)d_in[2], (const float*)d_in[7],  (const float*)d_in[12]};
    const float* Wc[3]  = {(const float*)d_in[3], (const float*)d_in[8],  (const float*)d_in[13]};
    const float* bc[3]  = {(const float*)d_in[4], (const float*)d_in[9],  (const float*)d_in[14]};
    const float* Fp[3]  = {(const float*)d_in[5], (const float*)d_in[10], (const float*)d_in[15]};
    const float* mha_iw = (const float*)d_in[16];
    const float* mha_ib = (const float*)d_in[17];
    const float* mha_ow = (const float*)d_in[18];
    const float* mha_ob = (const float*)d_in[19];
    const float* fus_W  = (const float*)d_in[20];
    const float* fus_b  = (const float*)d_in[21];
    float* outp = (float*)d_out;

    float *xd, *t1, *t2, *sre, *sim, *chre, *chim, *mre, *mim;
    float *scre, *scim, *ore, *oim, *stack, *qkvb, *attnb, *corr, *fw, *Dm, *Im;
    cudaGetSymbolAddress((void**)&xd, g_xd);
    cudaGetSymbolAddress((void**)&t1, g_t1);
    cudaGetSymbolAddress((void**)&t2, g_t2);
    cudaGetSymbolAddress((void**)&sre, g_sre);
    cudaGetSymbolAddress((void**)&sim, g_sim);
    cudaGetSymbolAddress((void**)&chre, g_chre);
    cudaGetSymbolAddress((void**)&chim, g_chim);
    cudaGetSymbolAddress((void**)&mre, g_mre);
    cudaGetSymbolAddress((void**)&mim, g_mim);
    cudaGetSymbolAddress((void**)&scre, g_scre);
    cudaGetSymbolAddress((void**)&scim, g_scim);
    cudaGetSymbolAddress((void**)&ore, g_ore);
    cudaGetSymbolAddress((void**)&oim, g_oim);
    cudaGetSymbolAddress((void**)&stack, g_stack);
    cudaGetSymbolAddress((void**)&qkvb, g_qkv);
    cudaGetSymbolAddress((void**)&attnb, g_attn);
    cudaGetSymbolAddress((void**)&corr, g_corr);
    cudaGetSymbolAddress((void**)&fw, g_fw);
    cudaGetSymbolAddress((void**)&Dm, g_Dm);
    cudaGetSymbolAddress((void**)&Im, g_Im);

    const float scale = 0.03125f;  // 1/sqrt(1024)

    // setup
    dctinit_k<<<(int)((SS + 255) / 256), 256>>>(Dm, Im);
    for (int d = 0; d < 3; d++)
        fwsoft_k<<<(E + 255) / 256, 256>>>(Fp[d], fw + (long)d * C * E);

    const dim3 tpb_t(32, 8);

    for (int d = 0; d < 3; d++) {
        const float* fwd = fw + (long)d * C * E;
        // projection: xd = query @ Wp^T + bp   [4096,1024]
        gemm_k<true><<<ggrid(BS, E, 1), 256>>>(query, Wp[d], xd, bp[d],
            BS, E, E, E, E, E, 0, 0, 0, 1.f, 0.f);

        if (d == 0) {
            // ---- Fourier ----
            transpose_k<<<dim3(E / 32, S / 32, Bq), tpb_t>>>(xd, t1, S, E, SE, S, 0);
            fft_k<<<Bq * E, 512>>>(t1, nullptr, t1, t2, 0);
            transpose_k<<<dim3(S / 32, E / 32, Bq), tpb_t>>>(t1, sre, E, S, SE, E, 0);
            transpose_k<<<dim3(S / 32, E / 32, Bq), tpb_t>>>(t2, sim, E, S, SE, E, 0);
            conv_k<<<BS / 8, 128>>>(sre, Wc[d], bc[d], chre);
            conv_k<<<BS / 8, 128>>>(sim, Wc[d], bc[d], chim);
            gemm_k<false><<<ggrid(BS, E, 1), 256>>>(chre, fwd, mre, nullptr,
                BS, E, C, C, E, E, 0, 0, 0, 1.f, 0.f);
            gemm_k<false><<<ggrid(BS, E, 1), 256>>>(chim, fwd, mim, nullptr,
                BS, E, C, C, E, E, 0, 0, 0, 1.f, 0.f);
            // complex scores
            gemm_k<true><<<ggrid(S, S, Bq), 256>>>(mre, mre, scre, nullptr,
                S, S, E, E, E, S, SE, SE, SS, scale, 0.f);
            gemm_k<true><<<ggrid(S, S, Bq), 256>>>(mim, mim, scre, nullptr,
                S, S, E, E, E, S, SE, SE, SS, -scale, 1.f);
            gemm_k<true><<<ggrid(S, S, Bq), 256>>>(mre, mim, scim, nullptr,
                S, S, E, E, E, S, SE, SE, SS, scale, 0.f);
            gemm_k<true><<<ggrid(S, S, Bq), 256>>>(mim, mre, scim, nullptr,
                S, S, E, E, E, S, SE, SE, SS, scale, 1.f);
            softmax_cplx_k<<<BS, 256>>>(scre, scim);
            // complex out = cw @ v
            gemm_k<false><<<ggrid(S, E, Bq), 256>>>(scre, mre, ore, nullptr,
                S, E, S, S, E, E, SS, SE, SE, 1.f, 0.f);
            gemm_k<false><<<ggrid(S, E, Bq), 256>>>(scim, mim, ore, nullptr,
                S, E, S, S, E, E, SS, SE, SE, -1.f, 1.f);
            gemm_k<false><<<ggrid(S, E, Bq), 256>>>(scre, mim, oim, nullptr,
                S, E, S, S, E, E, SS, SE, SE, 1.f, 0.f);
            gemm_k<false><<<ggrid(S, E, Bq), 256>>>(scim, mre, oim, nullptr,
                S, E, S, S, E, E, SS, SE, SE, 1.f, 1.f);
            // ifft, take real, write into stack slot 0
            transpose_k<<<dim3(E / 32, S / 32, Bq), tpb_t>>>(ore, t1, S, E, SE, S, 0);
            transpose_k<<<dim3(E / 32, S / 32, Bq), tpb_t>>>(oim, t2, S, E, SE, S, 0);
            fft_k<<<Bq * E, 512>>>(t1, t2, t1, t2, 1);
            transpose_k<<<dim3(S / 32, E / 32, Bq), tpb_t>>>(t1, stack, E, S, (long)S * E3, E3, 0);
        } else if (d == 1) {
            // ---- Wavelet ----
            transpose_k<<<dim3(E / 32, S / 32, Bq), tpb_t>>>(xd, t1, S, E, SE, S, 0);
            haar_k<<<Bq * E, 512>>>(t1, t2);
            transpose_k<<<dim3(S / 32, E / 32, Bq), tpb_t>>>(t2, sre, E, S, SE, E, 0);
            conv_k<<<BS / 8, 128>>>(sre, Wc[d], bc[d], chre);
            gemm_k<false><<<ggrid(BS, E, 1), 256>>>(chre, fwd, mre, nullptr,
                BS, E, C, C, E, E, 0, 0, 0, 1.f, 0.f);
            gemm_k<true><<<ggrid(S, S, Bq), 256>>>(mre, mre, scre, nullptr,
                S, S, E, E, E, S, SE, SE, SS, scale, 0.f);
            softmax_real_k<<<BS, 256>>>(scre);
            gemm_k<false><<<ggrid(S, E, Bq), 256>>>(scre, mre, stack + E, nullptr,
                S, E, S, S, E, E3, SS, SE, (long)S * E3, 1.f, 0.f);
        } else {
            // ---- Cosine ----
            gemm_k<false><<<ggrid(S, E, Bq), 256>>>(Dm, xd, sre, nullptr,
                S, E, S, S, E, E, 0, SE, SE, 1.f, 0.f);
            conv_k<<<BS / 8, 128>>>(sre, Wc[d], bc[d], chre);
            gemm_k<false><<<ggrid(BS, E, 1), 256>>>(chre, fwd, mre, nullptr,
                BS, E, C, C, E, E, 0, 0, 0, 1.f, 0.f);
            gemm_k<true><<<ggrid(S, S, Bq), 256>>>(mre, mre, scre, nullptr,
                S, S, E, E, E, S, SE, SE, SS, scale, 0.f);
            softmax_real_k<<<BS, 256>>>(scre);
            gemm_k<false><<<ggrid(S, E, Bq), 256>>>(scre, mre, ore, nullptr,
                S, E, S, S, E, E, SS, SE, SE, 1.f, 0.f);
            gemm_k<false><<<ggrid(S, E, Bq), 256>>>(Im, ore, stack + 2 * E, nullptr,
                S, E, S, S, E, E3, 0, SE, (long)S * E3, 1.f, 0.f);
        }
    }

    // ---- cross-domain MHA over L=3 ----
    gemm_k<true><<<ggrid(BS * 3, E3, 1), 256>>>(stack, mha_iw, qkvb, mha_ib,
        BS * 3, E3, E, E, E, E3, 0, 0, 0, 1.f, 0.f);
    mha_k<<<(BS * NH) / 8, 256>>>(qkvb, attnb);
    gemm_k<true><<<ggrid(BS * 3, E, 1), 256>>>(attnb, mha_ow, corr, mha_ob,
        BS * 3, E, E, E, E, E, 0, 0, 0, 1.f, 0.f);
    gemm_k<true><<<ggrid(BS, E, 1), 256>>>(corr, fus_W, outp, fus_b,
        BS, E, E3, E3, E3, E, 0, 0, 0, 1.f, 0.f);
}